// round 8
// baseline (speedup 1.0000x reference)
#include <cuda_runtime.h>
#include <cuda_bf16.h>
#include <math.h>
#include <stdint.h>

#define BATCH 4
#define SEQ 4096
#define NH 16
#define HD 64
#define DIM 1024
#define BH (BATCH*NH)          // 64
#define CHUNK 64
#define NCHUNK (SEQ/CHUNK)     // 64
#define MTOT (BATCH*SEQ)       // 16384
#define FSCALE 0.35355339059327373f   // 64^-0.25

// ================= helpers =================
__device__ __forceinline__ uint32_t smem_u32(const void* p) {
    uint32_t a;
    asm("{ .reg .u64 t; cvta.to.shared.u64 t, %1; cvt.u32.u64 %0, t; }" : "=r"(a) : "l"(p));
    return a;
}
#define SW128(off) ((off) ^ (((off) >> 3) & 0x70))

__device__ __forceinline__ void cp16(uint32_t sa, const void* g) {
    asm volatile("cp.async.cg.shared.global [%0], [%1], 16;\n" :: "r"(sa), "l"(g) : "memory");
}
#define CP_COMMIT()  asm volatile("cp.async.commit_group;\n" ::: "memory")
#define CP_WAIT(n)   asm volatile("cp.async.wait_group %0;\n" :: "n"(n) : "memory")

__device__ __forceinline__ void ldsm4(uint32_t* r, uint32_t addr) {
    asm volatile("ldmatrix.sync.aligned.m8n8.x4.shared.b16 {%0,%1,%2,%3}, [%4];"
        : "=r"(r[0]), "=r"(r[1]), "=r"(r[2]), "=r"(r[3]) : "r"(addr));
}
__device__ __forceinline__ void ldsm2(uint32_t* r, uint32_t addr) {
    asm volatile("ldmatrix.sync.aligned.m8n8.x2.shared.b16 {%0,%1}, [%2];"
        : "=r"(r[0]), "=r"(r[1]) : "r"(addr));
}
__device__ __forceinline__ void mma_bf16(float* c, const uint32_t* a, const uint32_t* b) {
    asm volatile(
        "mma.sync.aligned.m16n8k16.row.col.f32.bf16.bf16.f32 "
        "{%0,%1,%2,%3}, {%4,%5,%6,%7}, {%8,%9}, {%0,%1,%2,%3};"
        : "+f"(c[0]), "+f"(c[1]), "+f"(c[2]), "+f"(c[3])
        : "r"(a[0]), "r"(a[1]), "r"(a[2]), "r"(a[3]), "r"(b[0]), "r"(b[1]));
}

// ================= scratch =================
__device__ float g_qf  [ (size_t)BH * SEQ * HD ];
__device__ float g_kf  [ (size_t)BH * SEQ * HD ];
__device__ float g_vf  [ (size_t)BH * SEQ * HD ];
__device__ float g_Skv [ (size_t)BH * NCHUNK * HD * HD ];
__device__ float g_Pkv [ (size_t)BH * NCHUNK * HD * HD ];
__device__ float g_Sks [ (size_t)BH * NCHUNK * HD ];
__device__ float g_Pks [ (size_t)BH * NCHUNK * HD ];
__device__ __nv_bfloat16 g_xhi [ (size_t)MTOT * DIM ];
__device__ __nv_bfloat16 g_xlo [ (size_t)MTOT * DIM ];
__device__ __nv_bfloat16 g_wqhi[ (size_t)3 * DIM * DIM ];   // transposed [3072][1024]
__device__ __nv_bfloat16 g_wqlo[ (size_t)3 * DIM * DIM ];
__device__ __nv_bfloat16 g_wohi[ (size_t)DIM * DIM ];       // transposed [1024][1024]
__device__ __nv_bfloat16 g_wolo[ (size_t)DIM * DIM ];
__device__ __nv_bfloat16 g_ahi [ (size_t)MTOT * DIM ];
__device__ __nv_bfloat16 g_alo [ (size_t)MTOT * DIM ];

// ================= split kernels =================
__global__ __launch_bounds__(256) void split_kernel(const float* __restrict__ in,
                                                    __nv_bfloat16* __restrict__ hi,
                                                    __nv_bfloat16* __restrict__ lo)
{
    size_t i = ((size_t)blockIdx.x * 256 + threadIdx.x) * 4;
    float4 v = *(const float4*)(in + i);
    float a[4] = {v.x, v.y, v.z, v.w};
    __nv_bfloat16 h[4], l[4];
#pragma unroll
    for (int j = 0; j < 4; j++) {
        h[j] = __float2bfloat16(a[j]);
        l[j] = __float2bfloat16(a[j] - __bfloat162float(h[j]));
    }
    *(uint2*)(hi + i) = *(uint2*)h;
    *(uint2*)(lo + i) = *(uint2*)l;
}

// transpose + split: W [K][N] fp32 -> out [N][K] bf16 hi/lo
__global__ __launch_bounds__(256) void tsplit_kernel(const float* __restrict__ W,
                                                     __nv_bfloat16* __restrict__ hi,
                                                     __nv_bfloat16* __restrict__ lo,
                                                     int K, int N)
{
    __shared__ float t[32][33];
    int n0 = blockIdx.x * 32, k0 = blockIdx.y * 32;
    int tx = threadIdx.x, ty = threadIdx.y;   // 32 x 8
#pragma unroll
    for (int i = 0; i < 4; i++)
        t[ty + i * 8][tx] = W[(size_t)(k0 + ty + i * 8) * N + n0 + tx];
    __syncthreads();
#pragma unroll
    for (int i = 0; i < 4; i++) {
        float v = t[tx][ty + i * 8];
        __nv_bfloat16 h = __float2bfloat16(v);
        __nv_bfloat16 l = __float2bfloat16(v - __bfloat162float(h));
        size_t o = (size_t)(n0 + ty + i * 8) * K + k0 + tx;
        hi[o] = h; lo[o] = l;
    }
}

// ================= mma.sync bf16x3 GEMM (3-stage pipeline) =================
// C[M,Ncols] = A[M,1024] @ W[1024,Ncols]; A bf16 hi/lo row-major [M][1024],
// W transposed bf16 hi/lo [Ncols][1024]. Tile 128x128, KC=64, 3 stages.
// MODE 0: write C fp32.  MODE 1: fused RoPE+ELU featmap epilogue -> g_qf/g_kf/g_vf.
#define TILE_BYTES (128 * 64 * 2)           // 16 KB (128 rows x 128 B)
#define STAGE_BYTES (4 * TILE_BYTES)        // 64 KB
#define NSTAGE 3
#define GEMM_SMEM (NSTAGE * STAGE_BYTES)    // 192 KB
#define OFF_AHI 0
#define OFF_ALO TILE_BYTES
#define OFF_BHI (2 * TILE_BYTES)
#define OFF_BLO (3 * TILE_BYTES)

__device__ __forceinline__ void load_chunk(uint32_t stg,
    const __nv_bfloat16* __restrict__ Ahi, const __nv_bfloat16* __restrict__ Alo,
    const __nv_bfloat16* __restrict__ Bhi, const __nv_bfloat16* __restrict__ Blo,
    int m0, int n0, int k0, int tid)
{
#pragma unroll
    for (int i = 0; i < 4; i++) {
        int idx = tid + i * 256;
        int row = idx >> 3, cv = idx & 7;
        uint32_t sw = SW128((uint32_t)(row * 128 + cv * 16));
        size_t ao = (size_t)(m0 + row) * 1024 + k0 + cv * 8;
        size_t bo = (size_t)(n0 + row) * 1024 + k0 + cv * 8;
        cp16(stg + OFF_AHI + sw, Ahi + ao);
        cp16(stg + OFF_ALO + sw, Alo + ao);
        cp16(stg + OFF_BHI + sw, Bhi + bo);
        cp16(stg + OFF_BLO + sw, Blo + bo);
    }
}

template <int MODE>
__global__ __launch_bounds__(256, 1) void gemm_tc(
    const __nv_bfloat16* __restrict__ Ahi, const __nv_bfloat16* __restrict__ Alo,
    const __nv_bfloat16* __restrict__ Bhi, const __nv_bfloat16* __restrict__ Blo,
    float* __restrict__ C, int Ncols)
{
    extern __shared__ __align__(16) char smem[];
    const uint32_t sb = smem_u32(smem);
    const int tid = threadIdx.x;
    const int lane = tid & 31, wid = tid >> 5;
    const int wm = (wid & 1) * 64;      // warp m offset within 128
    const int wn = (wid >> 1) * 32;     // warp n offset within 128
    const int m0 = blockIdx.y * 128;
    const int n0 = blockIdx.x * 128;

    float acc[4][4][4];
#pragma unroll
    for (int i = 0; i < 4; i++)
#pragma unroll
        for (int j = 0; j < 4; j++)
#pragma unroll
            for (int r = 0; r < 4; r++) acc[i][j][r] = 0.f;

    const int la_r = lane & 15;          // A: row within 16
    const int la_h = lane >> 4;          // A: k half (0/1)
    const int lb_r = lane & 7;           // B: row within 8
    const int lb_h = (lane >> 3) & 1;    // B: k half (0/1)

    // prologue: chunks 0,1,2
    load_chunk(sb,                   Ahi, Alo, Bhi, Blo, m0, n0, 0,   tid); CP_COMMIT();
    load_chunk(sb + STAGE_BYTES,     Ahi, Alo, Bhi, Blo, m0, n0, 64,  tid); CP_COMMIT();
    load_chunk(sb + 2 * STAGE_BYTES, Ahi, Alo, Bhi, Blo, m0, n0, 128, tid); CP_COMMIT();

    int stage = 0;
    for (int c = 0; c < 16; c++) {
        if (c <= 13)      { CP_WAIT(2); }
        else if (c == 14) { CP_WAIT(1); }
        else              { CP_WAIT(0); }
        __syncthreads();

        const uint32_t stg = sb + stage * STAGE_BYTES;
#pragma unroll
        for (int ks = 0; ks < 4; ks++) {
            const int k0 = ks * 16;
            uint32_t ahi[4][4], alo[4][4];
#pragma unroll
            for (int mt = 0; mt < 4; mt++) {
                uint32_t off = SW128((uint32_t)((wm + mt * 16 + la_r) * 128 + (k0 + la_h * 8) * 2));
                ldsm4(ahi[mt], stg + OFF_AHI + off);
                ldsm4(alo[mt], stg + OFF_ALO + off);
            }
            uint32_t bhi[4][2], blo[4][2];
#pragma unroll
            for (int nt = 0; nt < 4; nt++) {
                uint32_t off = SW128((uint32_t)((wn + nt * 8 + lb_r) * 128 + (k0 + lb_h * 8) * 2));
                ldsm2(bhi[nt], stg + OFF_BHI + off);
                ldsm2(blo[nt], stg + OFF_BLO + off);
            }
#pragma unroll
            for (int mt = 0; mt < 4; mt++)
#pragma unroll
                for (int nt = 0; nt < 4; nt++) {
                    mma_bf16(acc[mt][nt], ahi[mt], bhi[nt]);
                    mma_bf16(acc[mt][nt], ahi[mt], blo[nt]);
                    mma_bf16(acc[mt][nt], alo[mt], bhi[nt]);
                }
        }
        __syncthreads();   // all warps done reading this stage
        if (c + 3 < 16) {
            load_chunk(sb + stage * STAGE_BYTES, Ahi, Alo, Bhi, Blo, m0, n0, (c + 3) * 64, tid);
            CP_COMMIT();
        }
        stage = (stage + 1 == NSTAGE) ? 0 : stage + 1;
    }

    const int rquad = lane >> 2, cpair = (lane & 3) * 2;

    if (MODE == 0) {
        // plain fp32 epilogue
#pragma unroll
        for (int mt = 0; mt < 4; mt++) {
#pragma unroll
            for (int nt = 0; nt < 4; nt++) {
                int row = m0 + wm + mt * 16 + rquad;
                int col = n0 + wn + nt * 8 + cpair;
                float2* p0 = (float2*)(C + (size_t)row * Ncols + col);
                float2* p1 = (float2*)(C + (size_t)(row + 8) * Ncols + col);
                *p0 = make_float2(acc[mt][nt][0], acc[mt][nt][1]);
                *p1 = make_float2(acc[mt][nt][2], acc[mt][nt][3]);
            }
        }
    } else {
        // fused featmap epilogue: stage smem is free now; stash fp32 tile there
        float* ct = (float*)smem;   // [128][128]
#pragma unroll
        for (int mt = 0; mt < 4; mt++) {
#pragma unroll
            for (int nt = 0; nt < 4; nt++) {
                int row = wm + mt * 16 + rquad;
                int col = wn + nt * 8 + cpair;
                *(float2*)&ct[row * 128 + col]       = make_float2(acc[mt][nt][0], acc[mt][nt][1]);
                *(float2*)&ct[(row + 8) * 128 + col] = make_float2(acc[mt][nt][2], acc[mt][nt][3]);
            }
        }
        __syncthreads();

        const int region = n0 >> 10;      // 0=q, 1=k, 2=v
        const int h0 = (n0 & 1023) >> 6;  // first head in this 128-col tile (2 heads)

        if (region < 2) {
            float* dst = (region == 0) ? g_qf : g_kf;
#pragma unroll 4
            for (int i = 0; i < 32; i++) {
                int p = i * 256 + tid;        // 8192 rope pairs in tile
                int row = p >> 6;             // 0..127
                int w = p & 63;
                int hh = w >> 5;              // head within tile
                int j = w & 31;               // rope pair index
                float x1 = ct[row * 128 + hh * 64 + j];
                float x2 = ct[row * 128 + hh * 64 + j + 32];
                int gm = m0 + row;
                int t = gm & 4095, b = gm >> 12;
                float inv = expf(-0.28782313662425572f * (float)j);   // ln(10000)/32
                float s, cc;
                sincosf((float)t * inv, &s, &cc);
                float a1 = (x1 * cc - x2 * s) * FSCALE;
                float a2 = (x1 * s + x2 * cc) * FSCALE;
                a1 = (a1 > 0.f) ? a1 + 1.f : expf(a1);
                a2 = (a2 > 0.f) ? a2 + 1.f : expf(a2);
                size_t o = ((size_t)(b * NH + h0 + hh) * SEQ + t) * 64 + j;
                dst[o] = a1; dst[o + 32] = a2;
            }
        } else {
#pragma unroll 4
            for (int i = 0; i < 64; i++) {
                int p = i * 256 + tid;        // 16384 elems
                int row = p >> 7, col = p & 127;
                int gm = m0 + row;
                int t = gm & 4095, b = gm >> 12;
                size_t o = ((size_t)(b * NH + h0 + (col >> 6)) * SEQ + t) * 64 + (col & 63);
                g_vf[o] = ct[row * 128 + col];
            }
        }
    }
}

// ================= per-chunk local sums =================
__global__ __launch_bounds__(256) void chunksum_kernel()
{
    const int c = blockIdx.x, bh = blockIdx.y;
    const int tid = threadIdx.x;
    __shared__ __align__(16) float ks[CHUNK][HD];
    __shared__ __align__(16) float vs[CHUNK][HD];

    const float* Kg = g_kf + ((size_t)bh * SEQ + c * CHUNK) * HD;
    const float* Vg = g_vf + ((size_t)bh * SEQ + c * CHUNK) * HD;

    const int row = tid >> 2, f0 = tid & 3;
#pragma unroll
    for (int i = 0; i < 4; i++) {
        int f = (f0 + i * 4) * 4;
        *(float4*)&ks[row][f] = *(const float4*)(Kg + row * 64 + f);
        *(float4*)&vs[row][f] = *(const float4*)(Vg + row * 64 + f);
    }
    __syncthreads();

    const int m = tid & 63;
    const int dbase = (tid >> 6) * 16;
    float acc[16];
#pragma unroll
    for (int i = 0; i < 16; i++) acc[i] = 0.f;

    for (int t = 0; t < CHUNK; t++) {
        float v = vs[t][m];
#pragma unroll
        for (int w = 0; w < 4; w++) {
            float4 kk = *(float4*)&ks[t][dbase + w * 4];
            acc[w * 4 + 0] += kk.x * v;
            acc[w * 4 + 1] += kk.y * v;
            acc[w * 4 + 2] += kk.z * v;
            acc[w * 4 + 3] += kk.w * v;
        }
    }

    float* S = g_Skv + ((size_t)bh * NCHUNK + c) * (HD * HD);
#pragma unroll
    for (int d = 0; d < 16; d++)
        S[(dbase + d) * 64 + m] = acc[d];

    if (tid < 64) {
        float s = 0.f;
        for (int t = 0; t < CHUNK; t++) s += ks[t][tid];
        g_Sks[((size_t)bh * NCHUNK + c) * HD + tid] = s;
    }
}

// ================= exclusive prefixes (one thread per chain) =================
__global__ __launch_bounds__(256) void prefix_kernel()
{
    int e = blockIdx.x * 256 + threadIdx.x;     // BH*4096 chains
    int bh = e >> 12, el = e & 4095;
    float run = 0.f;
    for (int c = 0; c < NCHUNK; c++) {
        size_t i = ((size_t)bh * NCHUNK + c) * (HD * HD) + el;
        g_Pkv[i] = run;
        run += g_Skv[i];
    }
}
__global__ __launch_bounds__(256) void prefix_ks_kernel()
{
    int e = blockIdx.x * 256 + threadIdx.x;     // BH*64 chains
    int bh = e >> 6, d = e & 63;
    float run = 0.f;
    for (int c = 0; c < NCHUNK; c++) {
        size_t i = ((size_t)bh * NCHUNK + c) * HD + d;
        g_Pks[i] = run;
        run += g_Sks[i];
    }
}

// ================= chunk attention (epilogue writes bf16 hi/lo) =================
__global__ __launch_bounds__(256) void attn_kernel()
{
    const int c = blockIdx.x, bh = blockIdx.y;
    const int tid = threadIdx.x;
    extern __shared__ float sm[];
    float* Qt   = sm;
    float* Kt   = Qt + 64 * 68;
    float* At   = Kt + 64 * 68;
    float* Vs   = At + 64 * 68;
    float* Ps   = Vs + 64 * 64;
    float* pks  = Ps + 64 * 64;
    float* dinv = pks + 64;

    const int t0 = c * CHUNK;
    const float* Qg   = g_qf + ((size_t)bh * SEQ + t0) * HD;
    const float* Kg   = g_kf + ((size_t)bh * SEQ + t0) * HD;
    const float* Vg   = g_vf + ((size_t)bh * SEQ + t0) * HD;
    const float* Pg   = g_Pkv + ((size_t)bh * NCHUNK + c) * (HD * HD);
    const float* pksg = g_Pks + ((size_t)bh * NCHUNK + c) * HD;

    const int row = tid >> 2, f0 = tid & 3;
#pragma unroll
    for (int i = 0; i < 4; i++) {
        int d = (f0 + i * 4) * 4;
        float4 q4 = *(const float4*)(Qg + row * 64 + d);
        Qt[(d + 0) * 68 + row] = q4.x;
        Qt[(d + 1) * 68 + row] = q4.y;
        Qt[(d + 2) * 68 + row] = q4.z;
        Qt[(d + 3) * 68 + row] = q4.w;
        float4 k4 = *(const float4*)(Kg + row * 64 + d);
        Kt[(d + 0) * 68 + row] = k4.x;
        Kt[(d + 1) * 68 + row] = k4.y;
        Kt[(d + 2) * 68 + row] = k4.z;
        Kt[(d + 3) * 68 + row] = k4.w;
        *(float4*)&Vs[row * 64 + d] = *(const float4*)(Vg + row * 64 + d);
        *(float4*)&Ps[row * 64 + d] = *(const float4*)(Pg + row * 64 + d);
    }
    if (tid < 64) pks[tid] = pksg[tid];
    __syncthreads();

    const int ty = tid >> 4, tx = tid & 15;
    const int rb = ty * 4, cb = tx * 4;

    float a[4][4];
#pragma unroll
    for (int i = 0; i < 4; i++)
#pragma unroll
        for (int j = 0; j < 4; j++) a[i][j] = 0.f;

    for (int d = 0; d < 64; d++) {
        float4 q4 = *(float4*)&Qt[d * 68 + rb];
        float4 k4 = *(float4*)&Kt[d * 68 + cb];
        float qv[4] = {q4.x, q4.y, q4.z, q4.w};
        float kv[4] = {k4.x, k4.y, k4.z, k4.w};
#pragma unroll
        for (int i = 0; i < 4; i++)
#pragma unroll
            for (int j = 0; j < 4; j++)
                a[i][j] += qv[i] * kv[j];
    }
#pragma unroll
    for (int i = 0; i < 4; i++)
#pragma unroll
        for (int j = 0; j < 4; j++) {
            int ti = rb + i, tj = cb + j;
            At[tj * 68 + ti] = (tj <= ti) ? a[i][j] : 0.f;
        }
    __syncthreads();

    if (tid < 64) {
        float s = 0.f;
        for (int tj = 0; tj < 64; tj++) s += At[tj * 68 + tid];
        for (int d = 0; d < 64; d++) s += Qt[d * 68 + tid] * pks[d];
        dinv[tid] = 1.0f / fmaxf(s, 1e-6f);
    }
    __syncthreads();

    float o[4][4];
#pragma unroll
    for (int i = 0; i < 4; i++)
#pragma unroll
        for (int j = 0; j < 4; j++) o[i][j] = 0.f;

    for (int tj = 0; tj < 64; tj++) {
        float4 a4 = *(float4*)&At[tj * 68 + rb];
        float4 v4 = *(float4*)&Vs[tj * 64 + cb];
        float av[4] = {a4.x, a4.y, a4.z, a4.w};
        float vv[4] = {v4.x, v4.y, v4.z, v4.w};
#pragma unroll
        for (int i = 0; i < 4; i++)
#pragma unroll
            for (int j = 0; j < 4; j++)
                o[i][j] += av[i] * vv[j];
    }
    for (int d = 0; d < 64; d++) {
        float4 q4 = *(float4*)&Qt[d * 68 + rb];
        float4 p4 = *(float4*)&Ps[d * 64 + cb];
        float qv[4] = {q4.x, q4.y, q4.z, q4.w};
        float pv[4] = {p4.x, p4.y, p4.z, p4.w};
#pragma unroll
        for (int i = 0; i < 4; i++)
#pragma unroll
            for (int j = 0; j < 4; j++)
                o[i][j] += qv[i] * pv[j];
    }

    const int b = bh >> 4, h = bh & 15;
#pragma unroll
    for (int i = 0; i < 4; i++) {
        int ti = rb + i;
        float di = dinv[ti];
        __nv_bfloat16 hv[4], lv[4];
#pragma unroll
        for (int j = 0; j < 4; j++) {
            float v = o[i][j] * di;
            hv[j] = __float2bfloat16(v);
            lv[j] = __float2bfloat16(v - __bfloat162float(hv[j]));
        }
        size_t oidx = (size_t)(b * SEQ + t0 + ti) * DIM + h * 64 + cb;
        *(uint2*)(g_ahi + oidx) = *(uint2*)hv;
        *(uint2*)(g_alo + oidx) = *(uint2*)lv;
    }
}

// ================= launch =================
extern "C" void kernel_launch(void* const* d_in, const int* in_sizes, int n_in,
                              void* d_out, int out_size)
{
    const float* x     = (const float*)d_in[0];
    const float* w_qkv = (const float*)d_in[1];
    const float* w_out = (const float*)d_in[2];
    float* out = (float*)d_out;

    __nv_bfloat16 *xhi, *xlo, *wqhi, *wqlo, *wohi, *wolo, *ahi, *alo;
    cudaGetSymbolAddress((void**)&xhi,  g_xhi);
    cudaGetSymbolAddress((void**)&xlo,  g_xlo);
    cudaGetSymbolAddress((void**)&wqhi, g_wqhi);
    cudaGetSymbolAddress((void**)&wqlo, g_wqlo);
    cudaGetSymbolAddress((void**)&wohi, g_wohi);
    cudaGetSymbolAddress((void**)&wolo, g_wolo);
    cudaGetSymbolAddress((void**)&ahi,  g_ahi);
    cudaGetSymbolAddress((void**)&alo,  g_alo);

    cudaFuncSetAttribute(gemm_tc<0>, cudaFuncAttributeMaxDynamicSharedMemorySize, GEMM_SMEM);
    cudaFuncSetAttribute(gemm_tc<1>, cudaFuncAttributeMaxDynamicSharedMemorySize, GEMM_SMEM);
    const int attn_smem = (64 * 68 * 3 + 64 * 64 * 2 + 128) * 4;
    cudaFuncSetAttribute(attn_kernel, cudaFuncAttributeMaxDynamicSharedMemorySize, attn_smem);

    // 0) splits
    split_kernel<<<(MTOT * DIM) / (256 * 4), 256>>>(x, xhi, xlo);
    tsplit_kernel<<<dim3(3 * DIM / 32, DIM / 32), dim3(32, 8)>>>(w_qkv, wqhi, wqlo, DIM, 3 * DIM);
    tsplit_kernel<<<dim3(DIM / 32, DIM / 32), dim3(32, 8)>>>(w_out, wohi, wolo, DIM, DIM);

    // 1) QKV projection + fused RoPE/ELU featmap -> g_qf/g_kf/g_vf
    gemm_tc<1><<<dim3(3 * DIM / 128, MTOT / 128), 256, GEMM_SMEM>>>(xhi, xlo, wqhi, wqlo, nullptr, 3 * DIM);

    // 2) per-chunk K^T V and sum(k)
    chunksum_kernel<<<dim3(NCHUNK, BH), 256>>>();

    // 3) exclusive prefixes
    prefix_kernel<<<(BH * HD * HD) / 256, 256>>>();
    prefix_ks_kernel<<<(BH * HD) / 256, 256>>>();

    // 4) chunk attention -> bf16 hi/lo activations
    attn_kernel<<<dim3(NCHUNK, BH), 256, attn_smem>>>();

    // 5) output projection
    gemm_tc<0><<<dim3(DIM / 128, MTOT / 128), 256, GEMM_SMEM>>>(ahi, alo, wohi, wolo, out, DIM);
}

// round 9
// speedup vs baseline: 1.0243x; 1.0243x over previous
#include <cuda_runtime.h>
#include <cuda_bf16.h>
#include <math.h>
#include <stdint.h>

#define BATCH 4
#define SEQ 4096
#define NH 16
#define HD 64
#define DIM 1024
#define BH (BATCH*NH)          // 64
#define CHUNK 64
#define NCHUNK (SEQ/CHUNK)     // 64
#define MTOT (BATCH*SEQ)       // 16384
#define FSCALE 0.35355339059327373f   // 64^-0.25

// ================= helpers =================
__device__ __forceinline__ uint32_t smem_u32(const void* p) {
    uint32_t a;
    asm("{ .reg .u64 t; cvta.to.shared.u64 t, %1; cvt.u32.u64 %0, t; }" : "=r"(a) : "l"(p));
    return a;
}
#define SW128(off) ((off) ^ (((off) >> 3) & 0x70))

__device__ __forceinline__ void cp16(uint32_t sa, const void* g) {
    asm volatile("cp.async.cg.shared.global [%0], [%1], 16;\n" :: "r"(sa), "l"(g) : "memory");
}
#define CP_COMMIT()  asm volatile("cp.async.commit_group;\n" ::: "memory")
#define CP_WAIT(n)   asm volatile("cp.async.wait_group %0;\n" :: "n"(n) : "memory")

__device__ __forceinline__ void ldsm4(uint32_t* r, uint32_t addr) {
    asm volatile("ldmatrix.sync.aligned.m8n8.x4.shared.b16 {%0,%1,%2,%3}, [%4];"
        : "=r"(r[0]), "=r"(r[1]), "=r"(r[2]), "=r"(r[3]) : "r"(addr));
}
__device__ __forceinline__ void mma_bf16(float* c, const uint32_t* a, const uint32_t* b) {
    asm volatile(
        "mma.sync.aligned.m16n8k16.row.col.f32.bf16.bf16.f32 "
        "{%0,%1,%2,%3}, {%4,%5,%6,%7}, {%8,%9}, {%0,%1,%2,%3};"
        : "+f"(c[0]), "+f"(c[1]), "+f"(c[2]), "+f"(c[3])
        : "r"(a[0]), "r"(a[1]), "r"(a[2]), "r"(a[3]), "r"(b[0]), "r"(b[1]));
}

// ================= scratch =================
__device__ float g_qf  [ (size_t)BH * SEQ * HD ];
__device__ float g_kf  [ (size_t)BH * SEQ * HD ];
__device__ float g_vf  [ (size_t)BH * SEQ * HD ];
__device__ float g_Skv [ (size_t)BH * NCHUNK * HD * HD ];
__device__ float g_Pkv [ (size_t)BH * NCHUNK * HD * HD ];
__device__ float g_Sks [ (size_t)BH * NCHUNK * HD ];
__device__ float g_Pks [ (size_t)BH * NCHUNK * HD ];
__device__ float g_cos [ (size_t)SEQ * 32 ];
__device__ float g_sin [ (size_t)SEQ * 32 ];
__device__ __nv_bfloat16 g_xhi [ (size_t)MTOT * DIM ];
__device__ __nv_bfloat16 g_xlo [ (size_t)MTOT * DIM ];
__device__ __nv_bfloat16 g_wqhi[ (size_t)3 * DIM * DIM ];   // transposed [3072][1024]
__device__ __nv_bfloat16 g_wqlo[ (size_t)3 * DIM * DIM ];
__device__ __nv_bfloat16 g_wohi[ (size_t)DIM * DIM ];       // transposed [1024][1024]
__device__ __nv_bfloat16 g_wolo[ (size_t)DIM * DIM ];
__device__ __nv_bfloat16 g_ahi [ (size_t)MTOT * DIM ];
__device__ __nv_bfloat16 g_alo [ (size_t)MTOT * DIM ];

// ================= rope table =================
__global__ __launch_bounds__(256) void rope_init()
{
    int idx = blockIdx.x * 256 + threadIdx.x;    // SEQ*32
    int j = idx & 31, t = idx >> 5;
    float inv = expf(-0.28782313662425572f * (float)j);   // ln(10000)/32
    float s, c;
    sincosf((float)t * inv, &s, &c);
    g_cos[idx] = c; g_sin[idx] = s;
}

// ================= split kernels =================
__global__ __launch_bounds__(256) void split_kernel(const float* __restrict__ in,
                                                    __nv_bfloat16* __restrict__ hi,
                                                    __nv_bfloat16* __restrict__ lo)
{
    size_t i = ((size_t)blockIdx.x * 256 + threadIdx.x) * 4;
    float4 v = *(const float4*)(in + i);
    float a[4] = {v.x, v.y, v.z, v.w};
    __nv_bfloat16 h[4], l[4];
#pragma unroll
    for (int j = 0; j < 4; j++) {
        h[j] = __float2bfloat16(a[j]);
        l[j] = __float2bfloat16(a[j] - __bfloat162float(h[j]));
    }
    *(uint2*)(hi + i) = *(uint2*)h;
    *(uint2*)(lo + i) = *(uint2*)l;
}

// transpose + split: W [K][N] fp32 -> out [N][K] bf16 hi/lo
__global__ __launch_bounds__(256) void tsplit_kernel(const float* __restrict__ W,
                                                     __nv_bfloat16* __restrict__ hi,
                                                     __nv_bfloat16* __restrict__ lo,
                                                     int K, int N)
{
    __shared__ float t[32][33];
    int n0 = blockIdx.x * 32, k0 = blockIdx.y * 32;
    int tx = threadIdx.x, ty = threadIdx.y;   // 32 x 8
#pragma unroll
    for (int i = 0; i < 4; i++)
        t[ty + i * 8][tx] = W[(size_t)(k0 + ty + i * 8) * N + n0 + tx];
    __syncthreads();
#pragma unroll
    for (int i = 0; i < 4; i++) {
        float v = t[tx][ty + i * 8];
        __nv_bfloat16 h = __float2bfloat16(v);
        __nv_bfloat16 l = __float2bfloat16(v - __bfloat162float(h));
        size_t o = (size_t)(n0 + ty + i * 8) * K + k0 + tx;
        hi[o] = h; lo[o] = l;
    }
}

// ================= mma.sync bf16x3 GEMM (KC=32, 3 stages, 2 CTAs/SM) ==========
// Stage row layout: 128 B per row = hi(64B: 32 k-elems) | lo(64B).
// A tile: 128 rows(m) x 128B = 16 KB; B tile: 128 rows(n) x 128B = 16 KB.
#define STAGE_BYTES 32768
#define NSTAGE 3
#define GEMM_SMEM (NSTAGE * STAGE_BYTES)    // 96 KB
#define OFF_B 16384
#define KCH 32
#define NCH (1024 / KCH)                    // 32 chunks

__device__ __forceinline__ void load_chunk(uint32_t stg,
    const __nv_bfloat16* __restrict__ Ahi, const __nv_bfloat16* __restrict__ Alo,
    const __nv_bfloat16* __restrict__ Bhi, const __nv_bfloat16* __restrict__ Blo,
    int m0, int n0, int k0, int tid)
{
#pragma unroll
    for (int i = 0; i < 8; i++) {
        int idx = tid + i * 256;              // 0..2047
        int tile = idx >> 10;                 // 0=A, 1=B
        int rem = idx & 1023;
        int row = rem >> 3, cv = rem & 7;
        uint32_t dst = stg + tile * OFF_B + SW128((uint32_t)(row * 128 + cv * 16));
        const __nv_bfloat16* base;
        int kk = k0 + (cv & 3) * 8;
        if (tile == 0) base = (cv < 4) ? Ahi : Alo;
        else           base = (cv < 4) ? Bhi : Blo;
        int grow = (tile == 0) ? (m0 + row) : (n0 + row);
        cp16(dst, base + (size_t)grow * 1024 + kk);
    }
}

template <int MODE>
__global__ __launch_bounds__(256, 2) void gemm_tc(
    const __nv_bfloat16* __restrict__ Ahi, const __nv_bfloat16* __restrict__ Alo,
    const __nv_bfloat16* __restrict__ Bhi, const __nv_bfloat16* __restrict__ Blo,
    float* __restrict__ C, int Ncols)
{
    extern __shared__ __align__(16) char smem[];
    const uint32_t sb = smem_u32(smem);
    const int tid = threadIdx.x;
    const int lane = tid & 31, wid = tid >> 5;
    const int wm = (wid & 1) * 64;      // warp m offset within 128
    const int wn = (wid >> 1) * 32;     // warp n offset within 128
    const int m0 = blockIdx.y * 128;
    const int n0 = blockIdx.x * 128;

    float acc[4][4][4];
#pragma unroll
    for (int i = 0; i < 4; i++)
#pragma unroll
        for (int j = 0; j < 4; j++)
#pragma unroll
            for (int r = 0; r < 4; r++) acc[i][j][r] = 0.f;

    const int la_r = lane & 15;                       // A row within 16
    const int la_h = lane >> 4;                       // A k half
    const int lb_row = ((lane >> 4) & 1) * 8 + (lane & 7);  // B row sel for x4 (2 tiles)
    const int lb_k = (lane >> 3) & 1;                 // B k half

    load_chunk(sb,                   Ahi, Alo, Bhi, Blo, m0, n0, 0,        tid); CP_COMMIT();
    load_chunk(sb + STAGE_BYTES,     Ahi, Alo, Bhi, Blo, m0, n0, KCH,      tid); CP_COMMIT();
    load_chunk(sb + 2 * STAGE_BYTES, Ahi, Alo, Bhi, Blo, m0, n0, 2 * KCH,  tid); CP_COMMIT();

    int stage = 0;
    for (int c = 0; c < NCH; c++) {
        if (c <= NCH - 3)      { CP_WAIT(2); }
        else if (c == NCH - 2) { CP_WAIT(1); }
        else                   { CP_WAIT(0); }
        __syncthreads();

        const uint32_t stg = sb + stage * STAGE_BYTES;
#pragma unroll
        for (int ks = 0; ks < 2; ks++) {
            const int kb = ks * 32 + la_h * 16;      // byte col (hi)
            uint32_t ahi[4][4], alo[4][4];
#pragma unroll
            for (int mt = 0; mt < 4; mt++) {
                uint32_t ro = (uint32_t)((wm + mt * 16 + la_r) * 128);
                ldsm4(ahi[mt], stg + SW128(ro + kb));
                ldsm4(alo[mt], stg + SW128(ro + kb + 64));
            }
            const int kbb = ks * 32 + lb_k * 16;
#pragma unroll
            for (int ntp = 0; ntp < 2; ntp++) {
                uint32_t bh[4], bl[4];
                uint32_t ro = (uint32_t)((wn + ntp * 16 + lb_row) * 128);
                ldsm4(bh, stg + OFF_B + SW128(ro + kbb));
                ldsm4(bl, stg + OFF_B + SW128(ro + kbb + 64));
#pragma unroll
                for (int mt = 0; mt < 4; mt++) {
                    mma_bf16(acc[mt][2 * ntp],     ahi[mt], bh);
                    mma_bf16(acc[mt][2 * ntp],     ahi[mt], bl);
                    mma_bf16(acc[mt][2 * ntp],     alo[mt], bh);
                    mma_bf16(acc[mt][2 * ntp + 1], ahi[mt], bh + 2);
                    mma_bf16(acc[mt][2 * ntp + 1], ahi[mt], bl + 2);
                    mma_bf16(acc[mt][2 * ntp + 1], alo[mt], bh + 2);
                }
            }
        }
        __syncthreads();
        if (c + 3 < NCH) {
            load_chunk(sb + stage * STAGE_BYTES, Ahi, Alo, Bhi, Blo, m0, n0, (c + 3) * KCH, tid);
            CP_COMMIT();
        }
        stage = (stage + 1 == NSTAGE) ? 0 : stage + 1;
    }

    const int rquad = lane >> 2, cpair = (lane & 3) * 2;

    if (MODE == 0) {
#pragma unroll
        for (int mt = 0; mt < 4; mt++) {
#pragma unroll
            for (int nt = 0; nt < 4; nt++) {
                int row = m0 + wm + mt * 16 + rquad;
                int col = n0 + wn + nt * 8 + cpair;
                float2* p0 = (float2*)(C + (size_t)row * Ncols + col);
                float2* p1 = (float2*)(C + (size_t)(row + 8) * Ncols + col);
                *p0 = make_float2(acc[mt][nt][0], acc[mt][nt][1]);
                *p1 = make_float2(acc[mt][nt][2], acc[mt][nt][3]);
            }
        }
    } else {
        // fused featmap epilogue: stash fp32 tile in (now free) stage smem
        float* ct = (float*)smem;   // [128][128]
#pragma unroll
        for (int mt = 0; mt < 4; mt++) {
#pragma unroll
            for (int nt = 0; nt < 4; nt++) {
                int row = wm + mt * 16 + rquad;
                int col = wn + nt * 8 + cpair;
                *(float2*)&ct[row * 128 + col]       = make_float2(acc[mt][nt][0], acc[mt][nt][1]);
                *(float2*)&ct[(row + 8) * 128 + col] = make_float2(acc[mt][nt][2], acc[mt][nt][3]);
            }
        }
        __syncthreads();

        const int region = n0 >> 10;      // 0=q, 1=k, 2=v
        const int h0 = (n0 & 1023) >> 6;  // first head in this tile (2 heads)

        if (region < 2) {
            float* dst = (region == 0) ? g_qf : g_kf;
#pragma unroll 4
            for (int i = 0; i < 32; i++) {
                int p = i * 256 + tid;        // 8192 rope pairs
                int row = p >> 6;
                int w = p & 63;
                int hh = w >> 5;
                int j = w & 31;
                float x1 = ct[row * 128 + hh * 64 + j];
                float x2 = ct[row * 128 + hh * 64 + j + 32];
                int gm = m0 + row;
                int t = gm & 4095, b = gm >> 12;
                float cc = g_cos[t * 32 + j];
                float s  = g_sin[t * 32 + j];
                float a1 = (x1 * cc - x2 * s) * FSCALE;
                float a2 = (x1 * s + x2 * cc) * FSCALE;
                a1 = (a1 > 0.f) ? a1 + 1.f : __expf(a1);
                a2 = (a2 > 0.f) ? a2 + 1.f : __expf(a2);
                size_t o = ((size_t)(b * NH + h0 + hh) * SEQ + t) * 64 + j;
                dst[o] = a1; dst[o + 32] = a2;
            }
        } else {
#pragma unroll 4
            for (int i = 0; i < 64; i++) {
                int p = i * 256 + tid;
                int row = p >> 7, col = p & 127;
                int gm = m0 + row;
                int t = gm & 4095, b = gm >> 12;
                size_t o = ((size_t)(b * NH + h0 + (col >> 6)) * SEQ + t) * 64 + (col & 63);
                g_vf[o] = ct[row * 128 + col];
            }
        }
    }
}

// ================= per-chunk local sums =================
__global__ __launch_bounds__(256) void chunksum_kernel()
{
    const int c = blockIdx.x, bh = blockIdx.y;
    const int tid = threadIdx.x;
    __shared__ __align__(16) float ks[CHUNK][HD];
    __shared__ __align__(16) float vs[CHUNK][HD];

    const float* Kg = g_kf + ((size_t)bh * SEQ + c * CHUNK) * HD;
    const float* Vg = g_vf + ((size_t)bh * SEQ + c * CHUNK) * HD;

    const int row = tid >> 2, f0 = tid & 3;
#pragma unroll
    for (int i = 0; i < 4; i++) {
        int f = (f0 + i * 4) * 4;
        *(float4*)&ks[row][f] = *(const float4*)(Kg + row * 64 + f);
        *(float4*)&vs[row][f] = *(const float4*)(Vg + row * 64 + f);
    }
    __syncthreads();

    const int m = tid & 63;
    const int dbase = (tid >> 6) * 16;
    float acc[16];
#pragma unroll
    for (int i = 0; i < 16; i++) acc[i] = 0.f;

    for (int t = 0; t < CHUNK; t++) {
        float v = vs[t][m];
#pragma unroll
        for (int w = 0; w < 4; w++) {
            float4 kk = *(float4*)&ks[t][dbase + w * 4];
            acc[w * 4 + 0] += kk.x * v;
            acc[w * 4 + 1] += kk.y * v;
            acc[w * 4 + 2] += kk.z * v;
            acc[w * 4 + 3] += kk.w * v;
        }
    }

    float* S = g_Skv + ((size_t)bh * NCHUNK + c) * (HD * HD);
#pragma unroll
    for (int d = 0; d < 16; d++)
        S[(dbase + d) * 64 + m] = acc[d];

    if (tid < 64) {
        float s = 0.f;
        for (int t = 0; t < CHUNK; t++) s += ks[t][tid];
        g_Sks[((size_t)bh * NCHUNK + c) * HD + tid] = s;
    }
}

// ================= exclusive prefixes (one thread per chain) =================
__global__ __launch_bounds__(256) void prefix_kernel()
{
    int e = blockIdx.x * 256 + threadIdx.x;     // BH*4096 chains
    int bh = e >> 12, el = e & 4095;
    float run = 0.f;
    for (int c = 0; c < NCHUNK; c++) {
        size_t i = ((size_t)bh * NCHUNK + c) * (HD * HD) + el;
        g_Pkv[i] = run;
        run += g_Skv[i];
    }
}
__global__ __launch_bounds__(256) void prefix_ks_kernel()
{
    int e = blockIdx.x * 256 + threadIdx.x;     // BH*64 chains
    int bh = e >> 6, d = e & 63;
    float run = 0.f;
    for (int c = 0; c < NCHUNK; c++) {
        size_t i = ((size_t)bh * NCHUNK + c) * HD + d;
        g_Pks[i] = run;
        run += g_Sks[i];
    }
}

// ================= chunk attention (epilogue writes bf16 hi/lo) =================
__global__ __launch_bounds__(256) void attn_kernel()
{
    const int c = blockIdx.x, bh = blockIdx.y;
    const int tid = threadIdx.x;
    extern __shared__ float sm[];
    float* Qt   = sm;
    float* Kt   = Qt + 64 * 68;
    float* At   = Kt + 64 * 68;
    float* Vs   = At + 64 * 68;
    float* Ps   = Vs + 64 * 64;
    float* pks  = Ps + 64 * 64;
    float* dinv = pks + 64;

    const int t0 = c * CHUNK;
    const float* Qg   = g_qf + ((size_t)bh * SEQ + t0) * HD;
    const float* Kg   = g_kf + ((size_t)bh * SEQ + t0) * HD;
    const float* Vg   = g_vf + ((size_t)bh * SEQ + t0) * HD;
    const float* Pg   = g_Pkv + ((size_t)bh * NCHUNK + c) * (HD * HD);
    const float* pksg = g_Pks + ((size_t)bh * NCHUNK + c) * HD;

    const int row = tid >> 2, f0 = tid & 3;
#pragma unroll
    for (int i = 0; i < 4; i++) {
        int d = (f0 + i * 4) * 4;
        float4 q4 = *(const float4*)(Qg + row * 64 + d);
        Qt[(d + 0) * 68 + row] = q4.x;
        Qt[(d + 1) * 68 + row] = q4.y;
        Qt[(d + 2) * 68 + row] = q4.z;
        Qt[(d + 3) * 68 + row] = q4.w;
        float4 k4 = *(const float4*)(Kg + row * 64 + d);
        Kt[(d + 0) * 68 + row] = k4.x;
        Kt[(d + 1) * 68 + row] = k4.y;
        Kt[(d + 2) * 68 + row] = k4.z;
        Kt[(d + 3) * 68 + row] = k4.w;
        *(float4*)&Vs[row * 64 + d] = *(const float4*)(Vg + row * 64 + d);
        *(float4*)&Ps[row * 64 + d] = *(const float4*)(Pg + row * 64 + d);
    }
    if (tid < 64) pks[tid] = pksg[tid];
    __syncthreads();

    const int ty = tid >> 4, tx = tid & 15;
    const int rb = ty * 4, cb = tx * 4;

    float a[4][4];
#pragma unroll
    for (int i = 0; i < 4; i++)
#pragma unroll
        for (int j = 0; j < 4; j++) a[i][j] = 0.f;

    for (int d = 0; d < 64; d++) {
        float4 q4 = *(float4*)&Qt[d * 68 + rb];
        float4 k4 = *(float4*)&Kt[d * 68 + cb];
        float qv[4] = {q4.x, q4.y, q4.z, q4.w};
        float kv[4] = {k4.x, k4.y, k4.z, k4.w};
#pragma unroll
        for (int i = 0; i < 4; i++)
#pragma unroll
            for (int j = 0; j < 4; j++)
                a[i][j] += qv[i] * kv[j];
    }
#pragma unroll
    for (int i = 0; i < 4; i++)
#pragma unroll
        for (int j = 0; j < 4; j++) {
            int ti = rb + i, tj = cb + j;
            At[tj * 68 + ti] = (tj <= ti) ? a[i][j] : 0.f;
        }
    __syncthreads();

    if (tid < 64) {
        float s = 0.f;
        for (int tj = 0; tj < 64; tj++) s += At[tj * 68 + tid];
        for (int d = 0; d < 64; d++) s += Qt[d * 68 + tid] * pks[d];
        dinv[tid] = 1.0f / fmaxf(s, 1e-6f);
    }
    __syncthreads();

    float o[4][4];
#pragma unroll
    for (int i = 0; i < 4; i++)
#pragma unroll
        for (int j = 0; j < 4; j++) o[i][j] = 0.f;

    for (int tj = 0; tj < 64; tj++) {
        float4 a4 = *(float4*)&At[tj * 68 + rb];
        float4 v4 = *(float4*)&Vs[tj * 64 + cb];
        float av[4] = {a4.x, a4.y, a4.z, a4.w};
        float vv[4] = {v4.x, v4.y, v4.z, v4.w};
#pragma unroll
        for (int i = 0; i < 4; i++)
#pragma unroll
            for (int j = 0; j < 4; j++)
                o[i][j] += av[i] * vv[j];
    }
    for (int d = 0; d < 64; d++) {
        float4 q4 = *(float4*)&Qt[d * 68 + rb];
        float4 p4 = *(float4*)&Ps[d * 64 + cb];
        float qv[4] = {q4.x, q4.y, q4.z, q4.w};
        float pv[4] = {p4.x, p4.y, p4.z, p4.w};
#pragma unroll
        for (int i = 0; i < 4; i++)
#pragma unroll
            for (int j = 0; j < 4; j++)
                o[i][j] += qv[i] * pv[j];
    }

    const int b = bh >> 4, h = bh & 15;
#pragma unroll
    for (int i = 0; i < 4; i++) {
        int ti = rb + i;
        float di = dinv[ti];
        __nv_bfloat16 hv[4], lv[4];
#pragma unroll
        for (int j = 0; j < 4; j++) {
            float v = o[i][j] * di;
            hv[j] = __float2bfloat16(v);
            lv[j] = __float2bfloat16(v - __bfloat162float(hv[j]));
        }
        size_t oidx = (size_t)(b * SEQ + t0 + ti) * DIM + h * 64 + cb;
        *(uint2*)(g_ahi + oidx) = *(uint2*)hv;
        *(uint2*)(g_alo + oidx) = *(uint2*)lv;
    }
}

// ================= launch =================
extern "C" void kernel_launch(void* const* d_in, const int* in_sizes, int n_in,
                              void* d_out, int out_size)
{
    const float* x     = (const float*)d_in[0];
    const float* w_qkv = (const float*)d_in[1];
    const float* w_out = (const float*)d_in[2];
    float* out = (float*)d_out;

    __nv_bfloat16 *xhi, *xlo, *wqhi, *wqlo, *wohi, *wolo, *ahi, *alo;
    cudaGetSymbolAddress((void**)&xhi,  g_xhi);
    cudaGetSymbolAddress((void**)&xlo,  g_xlo);
    cudaGetSymbolAddress((void**)&wqhi, g_wqhi);
    cudaGetSymbolAddress((void**)&wqlo, g_wqlo);
    cudaGetSymbolAddress((void**)&wohi, g_wohi);
    cudaGetSymbolAddress((void**)&wolo, g_wolo);
    cudaGetSymbolAddress((void**)&ahi,  g_ahi);
    cudaGetSymbolAddress((void**)&alo,  g_alo);

    cudaFuncSetAttribute(gemm_tc<0>, cudaFuncAttributeMaxDynamicSharedMemorySize, GEMM_SMEM);
    cudaFuncSetAttribute(gemm_tc<1>, cudaFuncAttributeMaxDynamicSharedMemorySize, GEMM_SMEM);
    const int attn_smem = (64 * 68 * 3 + 64 * 64 * 2 + 128) * 4;
    cudaFuncSetAttribute(attn_kernel, cudaFuncAttributeMaxDynamicSharedMemorySize, attn_smem);

    // 0) rope table + splits
    rope_init<<<(SEQ * 32) / 256, 256>>>();
    split_kernel<<<(MTOT * DIM) / (256 * 4), 256>>>(x, xhi, xlo);
    tsplit_kernel<<<dim3(3 * DIM / 32, DIM / 32), dim3(32, 8)>>>(w_qkv, wqhi, wqlo, DIM, 3 * DIM);
    tsplit_kernel<<<dim3(DIM / 32, DIM / 32), dim3(32, 8)>>>(w_out, wohi, wolo, DIM, DIM);

    // 1) QKV projection + fused RoPE/ELU featmap -> g_qf/g_kf/g_vf
    gemm_tc<1><<<dim3(3 * DIM / 128, MTOT / 128), 256, GEMM_SMEM>>>(xhi, xlo, wqhi, wqlo, nullptr, 3 * DIM);

    // 2) per-chunk K^T V and sum(k)
    chunksum_kernel<<<dim3(NCHUNK, BH), 256>>>();

    // 3) exclusive prefixes
    prefix_kernel<<<(BH * HD * HD) / 256, 256>>>();
    prefix_ks_kernel<<<(BH * HD) / 256, 256>>>();

    // 4) chunk attention -> bf16 hi/lo activations
    attn_kernel<<<dim3(NCHUNK, BH), 256, attn_smem>>>();

    // 5) output projection
    gemm_tc<0><<<dim3(DIM / 128, MTOT / 128), 256, GEMM_SMEM>>>(ahi, alo, wohi, wolo, out, DIM);
}